// round 10
// baseline (speedup 1.0000x reference)
#include <cuda_runtime.h>
#include <cuda_fp16.h>
#include <cuda_bf16.h>
#include <cstdint>
#include <cstddef>

#define BB 4096
#define NN 8192
#define DD 256

// ---- gemm1 tiling (fp16, in-kernel A conversion) ----
#define MT      64
#define KSPLIT  4
#define KPER    (NN / KSPLIT)     // 2048
#define KC      64
#define NCHUNK  (KPER / KC)       // 32
#define A_BYTES (64 * 128)        // A16: 64 m-rows x 64 fp16 = 8KB
#define B_BYTES (256 * 128)       // B16: 256 n-rows x 64 fp16 = 32KB
#define STG     (A_BYTES + B_BYTES)
#define GEMM_SMEM (3 * STG)       // 122880

// ---- mlp smem ----
#define MLP_IN_PL (128 * 512)     // 64KB per activation plane
#define MLP_W_PL  (64 * 512)      // 32KB (single fp16 W plane)
#define MLP_SMEM  (2 * MLP_IN_PL + MLP_W_PL)  // 163840

// ---- prep dispatch ----
#define PREP_SORT   0
#define PREP_CONVE  1                              // 512 blocks (64x64 transpose tiles)
#define PREP_CONVW  (PREP_CONVE + (NN / 64) * (DD / 64))
#define PREP_GRID   (PREP_CONVW + (3 * DD * DD) / 1024)   // +192

// -------------------- device scratch --------------------
__device__ __align__(256) int   g_labels_s[BB];
__device__ __align__(256) int   g_idx_s[BB];
__device__ int   g_total;
__device__ __align__(256) float g_rsumP[KSPLIT * BB];      // per-ksplit rowsum partials (sorted pos)
__device__ __align__(256) __half g_EhT[(size_t)DD * NN];   // E transposed [n][k], fp16
__device__ __align__(256) __half g_Wh[3 * DD * DD];        // W fp16 (single)
__device__ __align__(256) __half g_hHi[BB * DD];
__device__ __align__(256) __half g_hLo[BB * DD];
__device__ __align__(256) __half g_h2Hi[BB * DD];
__device__ __align__(256) __half g_h2Lo[BB * DD];
__device__ __align__(256) float g_part[(size_t)KSPLIT * BB * DD];

// -------------------- helpers --------------------
__device__ __forceinline__ uint32_t smem_u32(const void* p) {
    uint32_t a;
    asm("{ .reg .u64 t; cvta.to.shared.u64 t, %1; cvt.u32.u64 %0, t; }" : "=r"(a) : "l"(p));
    return a;
}
#define CP16(dst, src) \
    asm volatile("cp.async.cg.shared.global [%0], [%1], 16;" \
        :: "r"(dst), "l"(__cvta_generic_to_global(src)) : "memory")
#define CP_COMMIT() asm volatile("cp.async.commit_group;" ::: "memory")

#define LDSM_X4(r0, r1, r2, r3, addr) \
    asm volatile("ldmatrix.sync.aligned.m8n8.x4.shared.b16 {%0,%1,%2,%3}, [%4];" \
        : "=r"(r0), "=r"(r1), "=r"(r2), "=r"(r3) : "r"(addr))

#define MMA_F16(d, a0, a1, a2, a3, b0, b1) \
    asm volatile("mma.sync.aligned.m16n8k16.row.col.f32.f16.f16.f32 " \
        "{%0,%1,%2,%3}, {%4,%5,%6,%7}, {%8,%9}, {%0,%1,%2,%3};" \
        : "+f"((d)[0]), "+f"((d)[1]), "+f"((d)[2]), "+f"((d)[3]) \
        : "r"(a0), "r"(a1), "r"(a2), "r"(a3), "r"(b0), "r"(b1))

#define STS64(addr, u0, u1) \
    asm volatile("st.shared.v2.b32 [%0], {%1,%2};" :: "r"(addr), "r"(u0), "r"(u1) : "memory")

// ==================== 1) prep: sort + convE^T + convW ====================
__global__ void __launch_bounds__(256) prep_kernel(
    const int* __restrict__ labels, const int* __restrict__ nidx,
    const float* __restrict__ E,    const float* __restrict__ W,
    float* __restrict__ out_labels) {
    const int bid = blockIdx.x;
    const int t   = threadIdx.x;

    if (bid == PREP_SORT) {
        __shared__ int sc[256];
        int g0 = t * 16;
        int lab[16], nd[16];
        int c = 0;
#pragma unroll
        for (int j = 0; j < 16; j++) {
            lab[j] = labels[g0 + j];
            nd[j]  = nidx[g0 + j];
            c += (lab[j] != 0);
        }
        sc[t] = c;
        __syncthreads();
        for (int off = 1; off < 256; off <<= 1) {
            int v = sc[t];
            int add = (t >= off) ? sc[t - off] : 0;
            __syncthreads();
            sc[t] = v + add;
            __syncthreads();
        }
        int total = sc[255];
        int p     = sc[t] - c;
        if (t == 0) g_total = total;
#pragma unroll
        for (int j = 0; j < 16; j++) {
            int g = g0 + j;
            int dst;
            if (lab[j]) { dst = p; p++; }
            else        { dst = total + (g - p); }
            g_labels_s[dst] = lab[j];
            g_idx_s[dst]    = nd[j];
            if (out_labels) out_labels[dst] = (float)lab[j];
        }
    } else if (bid < PREP_CONVW) {
        // ---- convE^T: E[k][n] -> g_EhT[n][k] fp16, 64x64 tile ----
        __shared__ float tile[64][65];
        const int b2 = bid - PREP_CONVE;
        const int k0 = (b2 >> 2) * 64;
        const int n0 = (b2 & 3) * 64;
#pragma unroll
        for (int i = 0; i < 16; i++) {
            int idx = t + 256 * i;
            int kl = idx >> 6, nl = idx & 63;
            tile[kl][nl] = E[(size_t)(k0 + kl) * DD + n0 + nl];
        }
        __syncthreads();
        const int nl = t >> 2;
        const int ks = (t & 3) * 16;
        __half h[16];
#pragma unroll
        for (int j = 0; j < 16; j++)
            h[j] = __float2half_rn(tile[ks + j][nl]);
        uint4* dst = reinterpret_cast<uint4*>(g_EhT + (size_t)(n0 + nl) * NN + k0 + ks);
        dst[0] = *reinterpret_cast<uint4*>(h);
        dst[1] = *reinterpret_cast<uint4*>(h + 8);
    } else {
        // ---- convW: W -> fp16 ----
        size_t i = (size_t)(bid - PREP_CONVW) * 1024 + t * 4;
        float4 v = *reinterpret_cast<const float4*>(W + i);
        __half2* dst = reinterpret_cast<__half2*>(g_Wh + i);
        dst[0] = __float22half2_rn(make_float2(v.x, v.y));
        dst[1] = __float22half2_rn(make_float2(v.z, v.w));
    }
}

// ==================== 2) fp16 tensor GEMM, A converted in-kernel + fused rowsum ====================
// grid (KSPLIT, BB/MT), 256 threads: kb fast axis -> active tiles pack wave 1.
__global__ void __launch_bounds__(256, 1) gemm1_kernel(const float* __restrict__ A) {
    const int kb = blockIdx.x;
    const int m0 = blockIdx.y * MT;
    if (m0 >= g_total) return;

    extern __shared__ __align__(1024) char smem[];
    const uint32_t sb = smem_u32(smem);
    const int t = threadIdx.x, lane = t & 31, wid = t >> 5;
    const int wm = wid & 3, wn = wid >> 2;      // wn 0..1 (128-col bands)
    const size_t kBase = (size_t)kb * KPER;

    // A producer mapping: 4 threads per row; thread owns cols cseg + {0,16,32,48} (+j*16), 4 floats each
    const int r    = t >> 2;                    // A row 0..63
    const int cseg = (t & 3) * 4;               // starting float col
    const int node = g_idx_s[m0 + r];
    const float* rowA = A + (size_t)node * NN + kBase + cseg;

    float4 pf[4];
    auto prefetchA = [&](int c) {
        const float* p = rowA + (size_t)c * KC;
#pragma unroll
        for (int j = 0; j < 4; j++)
            pf[j] = __ldg(reinterpret_cast<const float4*>(p + j * 16));
    };

    float rsum = 0.f;
    auto convertA = [&](int c) {
        const uint32_t base = sb + (uint32_t)((c % 3) * STG);
        const uint32_t rowbase = base + r * 128;
        const uint32_t sw = (uint32_t)((r & 7) << 4);
#pragma unroll
        for (int j = 0; j < 4; j++) {
            __half2 h0 = __float22half2_rn(make_float2(pf[j].x, pf[j].y));
            __half2 h1 = __float22half2_rn(make_float2(pf[j].z, pf[j].w));
            float2 f0 = __half22float2(h0), f1 = __half22float2(h1);
            rsum += (f0.x + f0.y) + (f1.x + f1.y);
            uint32_t off = (uint32_t)((cseg + j * 16) * 2);
            STS64(rowbase + (off ^ sw),
                  *reinterpret_cast<uint32_t*>(&h0), *reinterpret_cast<uint32_t*>(&h1));
        }
    };

    auto loadB = [&](int c) {
        const uint32_t base = sb + (uint32_t)((c % 3) * STG) + A_BYTES;
        const size_t kOff = kBase + (size_t)c * KC;
#pragma unroll
        for (int i = 0; i < 8; i++) {
            int g = t + 256 * i;
            int n = g >> 3, sB = g & 7;
            uint32_t dst = base + n * 128 + (uint32_t)((sB * 16) ^ ((n & 7) << 4));
            CP16(dst, g_EhT + (size_t)n * NN + kOff + sB * 8);
        }
    };

    float acc[16][4];
#pragma unroll
    for (int f = 0; f < 16; f++)
#pragma unroll
        for (int q = 0; q < 4; q++) acc[f][q] = 0.f;

    auto compute_stage = [&](int c) {
        const uint32_t Ab = sb + (uint32_t)((c % 3) * STG);
        const uint32_t Bb = Ab + A_BYTES;
        const int q = lane >> 3, l7 = lane & 7;
        const int bnr   = wn * 128 + ((lane >> 4) << 3) + l7;
        const int bkoff = ((lane >> 3) & 1) * 16;
#pragma unroll
        for (int ks = 0; ks < 4; ks++) {
            const int am  = wm * 16 + (q & 1) * 8 + l7;
            const int akB = ks * 32 + (q >> 1) * 16;
            uint32_t a0, a1, a2, a3;
            LDSM_X4(a0, a1, a2, a3, Ab + am * 128 + (uint32_t)(akB ^ ((am & 7) << 4)));
            const int kbB = ks * 32 + bkoff;
#pragma unroll
            for (int jb = 0; jb < 8; jb++) {
                const int nrow = bnr + jb * 16;
                uint32_t b0, b1, b2, b3;
                LDSM_X4(b0, b1, b2, b3,
                        Bb + nrow * 128 + (uint32_t)(kbB ^ ((nrow & 7) << 4)));
                MMA_F16(acc[jb * 2],     a0, a1, a2, a3, b0, b1);
                MMA_F16(acc[jb * 2 + 1], a0, a1, a2, a3, b2, b3);
            }
        }
    };

    prefetchA(0);
    loadB(0); CP_COMMIT();
    loadB(1); CP_COMMIT();
    loadB(2); CP_COMMIT();
    for (int c = 0; c < NCHUNK; c++) {
        asm volatile("cp.async.wait_group 2;" ::: "memory");
        __syncthreads();
        convertA(c);
        if (c + 1 < NCHUNK) prefetchA(c + 1);
        __syncthreads();
        compute_stage(c);
        __syncthreads();
        if (c + 3 < NCHUNK) loadB(c + 3);
        CP_COMMIT();
    }

    // rowsum partial: reduce 4 threads of each row (lanes 4q..4q+3)
    rsum += __shfl_xor_sync(0xffffffffu, rsum, 1);
    rsum += __shfl_xor_sync(0xffffffffu, rsum, 2);
    if ((t & 3) == 0) g_rsumP[kb * BB + m0 + r] = rsum;

    float* pbase = g_part + ((size_t)kb * BB + m0) * DD;
    const int row = wm * 16 + (lane >> 2);
    const int cb  = wn * 128 + (lane & 3) * 2;
#pragma unroll
    for (int f = 0; f < 16; f++) {
        const int n = cb + f * 8;
        *reinterpret_cast<float2*>(pbase + (size_t)row * DD + n) =
            make_float2(acc[f][0], acc[f][1]);
        *reinterpret_cast<float2*>(pbase + (size_t)(row + 8) * DD + n) =
            make_float2(acc[f][2], acc[f][3]);
    }
}

// ==================== 3) finalize: reduce ksplits, normalize, gather, fp16-split ====================
__global__ void finalize_kernel(const float* __restrict__ E) {
    const int b = blockIdx.x;
    const int t = threadIdx.x;
    const int lab  = g_labels_s[b];
    const int node = g_idx_s[b];
    float v[4];
    if (lab) {
        float rs = g_rsumP[b] + g_rsumP[BB + b] + g_rsumP[2 * BB + b] + g_rsumP[3 * BB + b];
        float inv = 1.0f / rs;
        v[0] = v[1] = v[2] = v[3] = 0.f;
#pragma unroll
        for (int kb = 0; kb < KSPLIT; kb++) {
            float4 p = *reinterpret_cast<const float4*>(
                g_part + ((size_t)kb * BB + b) * DD + t * 4);
            v[0] += p.x; v[1] += p.y; v[2] += p.z; v[3] += p.w;
        }
#pragma unroll
        for (int j = 0; j < 4; j++) v[j] *= inv;
    } else {
        float4 p = *reinterpret_cast<const float4*>(E + (size_t)node * DD + t * 4);
        v[0] = p.x; v[1] = p.y; v[2] = p.z; v[3] = p.w;
    }
    size_t o = (size_t)b * DD + t * 4;
    __half hi[4], lo[4];
#pragma unroll
    for (int j = 0; j < 4; j++) {
        hi[j] = __float2half_rn(v[j]);
        lo[j] = __float2half_rn(v[j] - __half2float(hi[j]));
    }
    *reinterpret_cast<__half2*>(g_hHi + o)     = __halves2half2(hi[0], hi[1]);
    *reinterpret_cast<__half2*>(g_hHi + o + 2) = __halves2half2(hi[2], hi[3]);
    *reinterpret_cast<__half2*>(g_hLo + o)     = __halves2half2(lo[0], lo[1]);
    *reinterpret_cast<__half2*>(g_hLo + o + 2) = __halves2half2(lo[2], lo[3]);
}

// ==================== 4) MLP layer: fp16 x-split (2 MMAs) + bias + relu ====================
__global__ void __launch_bounds__(512, 1) mlp_kernel(
    const __half* __restrict__ inHi, const __half* __restrict__ inLo,
    const __half* __restrict__ Wh,   const float* __restrict__ bias,
    __half* __restrict__ outHi, __half* __restrict__ outLo,
    float* __restrict__ outF) {
    const int i0 = blockIdx.x * 128;
    const int o0 = blockIdx.y * 64;
    extern __shared__ __align__(1024) char smem[];
    const uint32_t sb = smem_u32(smem);
    const int t = threadIdx.x, lane = t & 31, wid = t >> 5;
    const int wm = wid & 7, wn = wid >> 3;   // 16 rows x 32 cols per warp
    const uint32_t sINhi = sb;
    const uint32_t sINlo = sb + MLP_IN_PL;
    const uint32_t sW    = sb + 2 * MLP_IN_PL;

    auto load_half = [&](int h) {
#pragma unroll
        for (int i = 0; i < 4; i++) {
            int g = t + 512 * i;
            int m = g >> 4, s = (g & 15) + h * 16;
            uint32_t off = m * 512 + (uint32_t)((s * 16) ^ ((m & 7) << 4));
            CP16(sINhi + off, inHi + (size_t)(i0 + m) * DD + s * 8);
            CP16(sINlo + off, inLo + (size_t)(i0 + m) * DD + s * 8);
        }
        {
            int g = t + 512 * (t < 512 ? 0 : 0);  // 1024 granules over 512 threads: 2 each
#pragma unroll
            for (int i = 0; i < 2; i++) {
                int gg = t + 512 * i;
                int n = gg >> 4, s = (gg & 15) + h * 16;
                uint32_t off = n * 512 + (uint32_t)((s * 16) ^ ((n & 7) << 4));
                CP16(sW + off, Wh + (size_t)(o0 + n) * DD + s * 8);
            }
            (void)g;
        }
    };

    float acc[4][4];
#pragma unroll
    for (int f = 0; f < 4; f++)
#pragma unroll
        for (int q = 0; q < 4; q++) acc[f][q] = 0.f;

    auto comp_half = [&](int h) {
        const int q = lane >> 3, l7 = lane & 7;
#pragma unroll
        for (int ksl = 0; ksl < 8; ksl++) {
            const int ks = h * 8 + ksl;
            uint32_t ah[4], al[4];
            {
                const int m  = wm * 16 + (q & 1) * 8 + l7;
                const int kB = ks * 32 + (q >> 1) * 16;
                const uint32_t off = m * 512 + (uint32_t)(kB ^ ((m & 7) << 4));
                LDSM_X4(ah[0], ah[1], ah[2], ah[3], sINhi + off);
                LDSM_X4(al[0], al[1], al[2], al[3], sINlo + off);
            }
            uint32_t bh[2][4];
#pragma unroll
            for (int nn = 0; nn < 2; nn++) {
                const int n  = wn * 32 + nn * 16 + (q >> 1) * 8 + l7;
                const int kB = ks * 32 + (q & 1) * 16;
                const uint32_t off = n * 512 + (uint32_t)(kB ^ ((n & 7) << 4));
                LDSM_X4(bh[nn][0], bh[nn][1], bh[nn][2], bh[nn][3], sW + off);
            }
#pragma unroll
            for (int nn = 0; nn < 2; nn++) {
                float* d0 = acc[nn * 2];
                float* d1 = acc[nn * 2 + 1];
                MMA_F16(d0, ah[0], ah[1], ah[2], ah[3], bh[nn][0], bh[nn][1]);
                MMA_F16(d0, al[0], al[1], al[2], al[3], bh[nn][0], bh[nn][1]);
                MMA_F16(d1, ah[0], ah[1], ah[2], ah[3], bh[nn][2], bh[nn][3]);
                MMA_F16(d1, al[0], al[1], al[2], al[3], bh[nn][2], bh[nn][3]);
            }
        }
    };

    load_half(0); CP_COMMIT();
    load_half(1); CP_COMMIT();
    asm volatile("cp.async.wait_group 1;" ::: "memory");
    __syncthreads();
    comp_half(0);
    asm volatile("cp.async.wait_group 0;" ::: "memory");
    __syncthreads();
    comp_half(1);

    const int row0 = i0 + wm * 16 + (lane >> 2);
#pragma unroll
    for (int f = 0; f < 4; f++) {
        const int col = o0 + wn * 32 + f * 8 + (lane & 3) * 2;
        const float b0 = bias[col], b1 = bias[col + 1];
        float y00 = fmaxf(acc[f][0] + b0, 0.f);
        float y01 = fmaxf(acc[f][1] + b1, 0.f);
        float y10 = fmaxf(acc[f][2] + b0, 0.f);
        float y11 = fmaxf(acc[f][3] + b1, 0.f);
        if (outF) {
            *reinterpret_cast<float2*>(outF + (size_t)row0 * DD + col) = make_float2(y00, y01);
            *reinterpret_cast<float2*>(outF + (size_t)(row0 + 8) * DD + col) = make_float2(y10, y11);
        } else {
            float y[4] = {y00, y01, y10, y11};
            __half hi[4], lo[4];
#pragma unroll
            for (int j = 0; j < 4; j++) {
                hi[j] = __float2half_rn(y[j]);
                lo[j] = __float2half_rn(y[j] - __half2float(hi[j]));
            }
            *reinterpret_cast<__half2*>(outHi + (size_t)row0 * DD + col) = __halves2half2(hi[0], hi[1]);
            *reinterpret_cast<__half2*>(outHi + (size_t)(row0 + 8) * DD + col) = __halves2half2(hi[2], hi[3]);
            *reinterpret_cast<__half2*>(outLo + (size_t)row0 * DD + col) = __halves2half2(lo[0], lo[1]);
            *reinterpret_cast<__half2*>(outLo + (size_t)(row0 + 8) * DD + col) = __halves2half2(lo[2], lo[3]);
        }
    }
}

// ==================== launch ====================
extern "C" void kernel_launch(void* const* d_in, const int* in_sizes, int n_in,
                              void* d_out, int out_size) {
    const int*   labels = (const int*)d_in[0];
    const int*   nidx   = (const int*)d_in[1];
    const float* A      = (const float*)d_in[2];
    const float* E      = (const float*)d_in[3];
    const float* W      = (const float*)d_in[4];
    const float* bias   = (const float*)d_in[5];

    float* out        = (float*)d_out;
    float* out_labels = nullptr;
    float* out_h      = out;
    if (out_size >= BB * DD + BB) {
        out_labels = out;
        out_h      = out + BB;
    }

    __half *hHi, *hLo, *h2Hi, *h2Lo, *Wh;
    cudaGetSymbolAddress((void**)&hHi,  g_hHi);
    cudaGetSymbolAddress((void**)&hLo,  g_hLo);
    cudaGetSymbolAddress((void**)&h2Hi, g_h2Hi);
    cudaGetSymbolAddress((void**)&h2Lo, g_h2Lo);
    cudaGetSymbolAddress((void**)&Wh,   g_Wh);

    cudaFuncSetAttribute(gemm1_kernel,
                         cudaFuncAttributeMaxDynamicSharedMemorySize, GEMM_SMEM);
    cudaFuncSetAttribute(mlp_kernel,
                         cudaFuncAttributeMaxDynamicSharedMemorySize, MLP_SMEM);

    prep_kernel<<<PREP_GRID, 256>>>(labels, nidx, E, W, out_labels);
    gemm1_kernel<<<dim3(KSPLIT, BB / MT), 256, GEMM_SMEM>>>(A);
    finalize_kernel<<<BB, 64>>>(E);
    mlp_kernel<<<dim3(BB / 128, DD / 64), 512, MLP_SMEM>>>(
        hHi, hLo, Wh, bias, h2Hi, h2Lo, nullptr);
    mlp_kernel<<<dim3(BB / 128, DD / 64), 512, MLP_SMEM>>>(
        h2Hi, h2Lo, Wh + DD * DD, bias + DD, hHi, hLo, nullptr);
    mlp_kernel<<<dim3(BB / 128, DD / 64), 512, MLP_SMEM>>>(
        hHi, hLo, Wh + 2 * DD * DD, bias + 2 * DD, nullptr, nullptr, out_h);
}

// round 11
// speedup vs baseline: 1.2322x; 1.2322x over previous
#include <cuda_runtime.h>
#include <cuda_fp16.h>
#include <cuda_bf16.h>
#include <cstdint>
#include <cstddef>

#define BB 4096
#define NN 8192
#define DD 256

// ---- gemm1 tiling (fp16) ----
#define MT      64
#define KSPLIT  4
#define KPER    (NN / KSPLIT)     // 2048
#define KC      64
#define NCHUNK  (KPER / KC)       // 32
#define A_BYTES (64 * 128)        // 64 m-rows x 64 fp16
#define B_BYTES (256 * 128)       // 256 n-rows x 64 fp16
#define STG     (A_BYTES + B_BYTES)
#define GEMM_SMEM (3 * STG)       // 122880

// ---- mlp smem ----
#define MLP_IN_PL (128 * 512)
#define MLP_W_PL  (64 * 512)
#define MLP_SMEM  (2 * MLP_IN_PL + MLP_W_PL)  // 163840

// ---- prep dispatch ----
#define PREP_SORT   0
#define PREP_CONVA  1                          // BB blocks
#define PREP_CONVE  (PREP_CONVA + BB)          // 512 blocks (64x64 transpose tiles)
#define PREP_CONVW  (PREP_CONVE + (NN / 64) * (DD / 64))
#define PREP_GRID   (PREP_CONVW + (3 * DD * DD) / 1024)

// -------------------- device scratch --------------------
__device__ __align__(256) int   g_labels_s[BB];
__device__ __align__(256) int   g_idx_s[BB];
__device__ __align__(256) int   g_perm[BB];
__device__ int   g_total;
__device__ __align__(256) float g_rsumF[BB];               // by ORIGINAL batch idx
__device__ __align__(256) __half g_Ah[(size_t)BB * NN];    // by ORIGINAL batch idx
__device__ __align__(256) __half g_EhT[(size_t)DD * NN];   // E transposed [n][k], fp16
__device__ __align__(256) __half g_Wh[3 * DD * DD];        // W fp16 (single)
__device__ __align__(256) __half g_hHi[BB * DD];
__device__ __align__(256) __half g_hLo[BB * DD];
__device__ __align__(256) __half g_h2Hi[BB * DD];
__device__ __align__(256) __half g_h2Lo[BB * DD];
__device__ __align__(256) float g_part[(size_t)KSPLIT * BB * DD];

// -------------------- helpers --------------------
__device__ __forceinline__ uint32_t smem_u32(const void* p) {
    uint32_t a;
    asm("{ .reg .u64 t; cvta.to.shared.u64 t, %1; cvt.u32.u64 %0, t; }" : "=r"(a) : "l"(p));
    return a;
}
#define CP16(dst, src) \
    asm volatile("cp.async.cg.shared.global [%0], [%1], 16;" \
        :: "r"(dst), "l"(__cvta_generic_to_global(src)) : "memory")
#define CP_COMMIT() asm volatile("cp.async.commit_group;" ::: "memory")

#define LDSM_X4(r0, r1, r2, r3, addr) \
    asm volatile("ldmatrix.sync.aligned.m8n8.x4.shared.b16 {%0,%1,%2,%3}, [%4];" \
        : "=r"(r0), "=r"(r1), "=r"(r2), "=r"(r3) : "r"(addr))

#define MMA_F16(d, a0, a1, a2, a3, b0, b1) \
    asm volatile("mma.sync.aligned.m16n8k16.row.col.f32.f16.f16.f32 " \
        "{%0,%1,%2,%3}, {%4,%5,%6,%7}, {%8,%9}, {%0,%1,%2,%3};" \
        : "+f"((d)[0]), "+f"((d)[1]), "+f"((d)[2]), "+f"((d)[3]) \
        : "r"(a0), "r"(a1), "r"(a2), "r"(a3), "r"(b0), "r"(b1))

// ==================== 1) fused prep: sort + convA + convE^T + convW ====================
__global__ void __launch_bounds__(256) prep_kernel(
    const int* __restrict__ labels, const int* __restrict__ nidx,
    const float* __restrict__ A,    const float* __restrict__ E,
    const float* __restrict__ W,    float* __restrict__ out_labels) {
    const int bid = blockIdx.x;
    const int t   = threadIdx.x;

    if (bid == PREP_SORT) {
        __shared__ int sc[256];
        int g0 = t * 16;
        int lab[16], nd[16];
        int c = 0;
#pragma unroll
        for (int j = 0; j < 16; j++) {
            lab[j] = labels[g0 + j];
            nd[j]  = nidx[g0 + j];
            c += (lab[j] != 0);
        }
        sc[t] = c;
        __syncthreads();
        for (int off = 1; off < 256; off <<= 1) {
            int v = sc[t];
            int add = (t >= off) ? sc[t - off] : 0;
            __syncthreads();
            sc[t] = v + add;
            __syncthreads();
        }
        int total = sc[255];
        int p     = sc[t] - c;
        if (t == 0) g_total = total;
#pragma unroll
        for (int j = 0; j < 16; j++) {
            int g = g0 + j;
            int dst;
            if (lab[j]) { dst = p; p++; }
            else        { dst = total + (g - p); }
            g_labels_s[dst] = lab[j];
            g_idx_s[dst]    = nd[j];
            g_perm[dst]     = g;
            if (out_labels) out_labels[dst] = (float)lab[j];
        }
    } else if (bid < PREP_CONVE) {
        // ---- convA: gather positive A rows -> fp16 + exact rounded rowsum ----
        const int b = bid - PREP_CONVA;
        if (labels[b] == 0) return;
        const int node = nidx[b];
        const float* src = A + (size_t)node * NN;
        __half* dst = g_Ah + (size_t)b * NN;
        float s = 0.f;
#pragma unroll
        for (int i = 0; i < 8; i++) {
            size_t idx = (size_t)t * 4 + (size_t)i * 1024;
            float4 v = *reinterpret_cast<const float4*>(src + idx);
            __half2 h0 = __float22half2_rn(make_float2(v.x, v.y));
            __half2 h1 = __float22half2_rn(make_float2(v.z, v.w));
            __half2* d = reinterpret_cast<__half2*>(dst + idx);
            d[0] = h0; d[1] = h1;
            float2 f0 = __half22float2(h0), f1 = __half22float2(h1);
            s += (f0.x + f0.y) + (f1.x + f1.y);
        }
#pragma unroll
        for (int off = 16; off > 0; off >>= 1)
            s += __shfl_down_sync(0xffffffffu, s, off);
        __shared__ float ws[8];
        if ((t & 31) == 0) ws[t >> 5] = s;
        __syncthreads();
        if (t == 0) {
            float tot = 0.f;
#pragma unroll
            for (int w = 0; w < 8; w++) tot += ws[w];
            g_rsumF[b] = tot;
        }
    } else if (bid < PREP_CONVW) {
        // ---- convE^T: E[k][n] -> g_EhT[n][k] fp16, 64x64 tile ----
        __shared__ float tile[64][65];
        const int b2 = bid - PREP_CONVE;
        const int k0 = (b2 >> 2) * 64;
        const int n0 = (b2 & 3) * 64;
#pragma unroll
        for (int i = 0; i < 16; i++) {
            int idx = t + 256 * i;
            int kl = idx >> 6, nl = idx & 63;
            tile[kl][nl] = E[(size_t)(k0 + kl) * DD + n0 + nl];
        }
        __syncthreads();
        const int nl = t >> 2;
        const int ks = (t & 3) * 16;
        __half h[16];
#pragma unroll
        for (int j = 0; j < 16; j++)
            h[j] = __float2half_rn(tile[ks + j][nl]);
        uint4* dst = reinterpret_cast<uint4*>(g_EhT + (size_t)(n0 + nl) * NN + k0 + ks);
        dst[0] = *reinterpret_cast<uint4*>(h);
        dst[1] = *reinterpret_cast<uint4*>(h + 8);
    } else {
        // ---- convW: W -> fp16 ----
        size_t i = (size_t)(bid - PREP_CONVW) * 1024 + t * 4;
        float4 v = *reinterpret_cast<const float4*>(W + i);
        __half2* dst = reinterpret_cast<__half2*>(g_Wh + i);
        dst[0] = __float22half2_rn(make_float2(v.x, v.y));
        dst[1] = __float22half2_rn(make_float2(v.z, v.w));
    }
}

// ==================== 2) fp16 tensor GEMM (round 9, unchanged) ====================
__global__ void __launch_bounds__(256, 1) gemm1_kernel() {
    const int kb = blockIdx.x;
    const int m0 = blockIdx.y * MT;
    if (m0 >= g_total) return;

    extern __shared__ __align__(1024) char smem[];
    const uint32_t sb = smem_u32(smem);
    const int t = threadIdx.x, lane = t & 31, wid = t >> 5;
    const int wm = wid & 3, wn = wid >> 2;      // wn 0..1 (128-col bands)
    const size_t kBase = (size_t)kb * KPER;

    const int mA = t >> 3, s8 = t & 7;
    const __half* rowA  = g_Ah + (size_t)g_perm[m0 + mA] * NN;
    const __half* rowA1 = g_Ah + (size_t)g_perm[m0 + mA + 32] * NN;

    float acc[16][4];
#pragma unroll
    for (int f = 0; f < 16; f++)
#pragma unroll
        for (int q = 0; q < 4; q++) acc[f][q] = 0.f;

    auto load_stage = [&](int c) {
        const uint32_t base = sb + (uint32_t)((c % 3) * STG);
        const size_t kOff = kBase + (size_t)c * KC;
        CP16(base + mA * 128 + (uint32_t)((s8 * 16) ^ ((mA & 7) << 4)),
             rowA + kOff + s8 * 8);
        {
            const int m1 = mA + 32;
            CP16(base + m1 * 128 + (uint32_t)((s8 * 16) ^ ((m1 & 7) << 4)),
                 rowA1 + kOff + s8 * 8);
        }
#pragma unroll
        for (int i = 0; i < 8; i++) {
            int g = t + 256 * i;
            int n = g >> 3, sB = g & 7;
            uint32_t dst = base + A_BYTES + n * 128 + (uint32_t)((sB * 16) ^ ((n & 7) << 4));
            CP16(dst, g_EhT + (size_t)n * NN + kOff + sB * 8);
        }
    };

    auto compute_stage = [&](int c) {
        const uint32_t Ab = sb + (uint32_t)((c % 3) * STG);
        const uint32_t Bb = Ab + A_BYTES;
        const int q = lane >> 3, l7 = lane & 7;
        const int bnr   = wn * 128 + ((lane >> 4) << 3) + l7;
        const int bkoff = ((lane >> 3) & 1) * 16;
#pragma unroll
        for (int ks = 0; ks < 4; ks++) {
            const int am  = wm * 16 + (q & 1) * 8 + l7;
            const int akB = ks * 32 + (q >> 1) * 16;
            uint32_t a0, a1, a2, a3;
            LDSM_X4(a0, a1, a2, a3, Ab + am * 128 + (uint32_t)(akB ^ ((am & 7) << 4)));
            const int kbB = ks * 32 + bkoff;
#pragma unroll
            for (int jb = 0; jb < 8; jb++) {
                const int nrow = bnr + jb * 16;
                uint32_t b0, b1, b2, b3;
                LDSM_X4(b0, b1, b2, b3,
                        Bb + nrow * 128 + (uint32_t)(kbB ^ ((nrow & 7) << 4)));
                MMA_F16(acc[jb * 2],     a0, a1, a2, a3, b0, b1);
                MMA_F16(acc[jb * 2 + 1], a0, a1, a2, a3, b2, b3);
            }
        }
    };

    load_stage(0); CP_COMMIT();
    load_stage(1); CP_COMMIT();
    load_stage(2); CP_COMMIT();
    for (int c = 0; c < NCHUNK; c++) {
        asm volatile("cp.async.wait_group 2;" ::: "memory");
        __syncthreads();
        compute_stage(c);
        __syncthreads();
        if (c + 3 < NCHUNK) load_stage(c + 3);
        CP_COMMIT();
    }

    float* pbase = g_part + ((size_t)kb * BB + m0) * DD;
    const int row = wm * 16 + (lane >> 2);
    const int cb  = wn * 128 + (lane & 3) * 2;
#pragma unroll
    for (int f = 0; f < 16; f++) {
        const int n = cb + f * 8;
        *reinterpret_cast<float2*>(pbase + (size_t)row * DD + n) =
            make_float2(acc[f][0], acc[f][1]);
        *reinterpret_cast<float2*>(pbase + (size_t)(row + 8) * DD + n) =
            make_float2(acc[f][2], acc[f][3]);
    }
}

// ==================== 3) finalize: reduce, normalize, gather, fp16-split ====================
__global__ void finalize_kernel(const float* __restrict__ E) {
    const int b = blockIdx.x;
    const int t = threadIdx.x;
    const int lab  = g_labels_s[b];
    const int node = g_idx_s[b];
    float v[4];
    if (lab) {
        float inv = 1.0f / g_rsumF[g_perm[b]];
        v[0] = v[1] = v[2] = v[3] = 0.f;
#pragma unroll
        for (int kb = 0; kb < KSPLIT; kb++) {
            float4 p = *reinterpret_cast<const float4*>(
                g_part + ((size_t)kb * BB + b) * DD + t * 4);
            v[0] += p.x; v[1] += p.y; v[2] += p.z; v[3] += p.w;
        }
#pragma unroll
        for (int j = 0; j < 4; j++) v[j] *= inv;
    } else {
        float4 p = *reinterpret_cast<const float4*>(E + (size_t)node * DD + t * 4);
        v[0] = p.x; v[1] = p.y; v[2] = p.z; v[3] = p.w;
    }
    size_t o = (size_t)b * DD + t * 4;
    __half hi[4], lo[4];
#pragma unroll
    for (int j = 0; j < 4; j++) {
        hi[j] = __float2half_rn(v[j]);
        lo[j] = __float2half_rn(v[j] - __half2float(hi[j]));
    }
    *reinterpret_cast<__half2*>(g_hHi + o)     = __halves2half2(hi[0], hi[1]);
    *reinterpret_cast<__half2*>(g_hHi + o + 2) = __halves2half2(hi[2], hi[3]);
    *reinterpret_cast<__half2*>(g_hLo + o)     = __halves2half2(lo[0], lo[1]);
    *reinterpret_cast<__half2*>(g_hLo + o + 2) = __halves2half2(lo[2], lo[3]);
}

// ==================== 4) MLP layer: fp16 x-split (2 MMAs) + bias + relu ====================
__global__ void __launch_bounds__(512, 1) mlp_kernel(
    const __half* __restrict__ inHi, const __half* __restrict__ inLo,
    const __half* __restrict__ Wh,   const float* __restrict__ bias,
    __half* __restrict__ outHi, __half* __restrict__ outLo,
    float* __restrict__ outF) {
    const int i0 = blockIdx.x * 128;
    const int o0 = blockIdx.y * 64;
    extern __shared__ __align__(1024) char smem[];
    const uint32_t sb = smem_u32(smem);
    const int t = threadIdx.x, lane = t & 31, wid = t >> 5;
    const int wm = wid & 7, wn = wid >> 3;   // 16 rows x 32 cols per warp
    const uint32_t sINhi = sb;
    const uint32_t sINlo = sb + MLP_IN_PL;
    const uint32_t sW    = sb + 2 * MLP_IN_PL;

    auto load_half = [&](int h) {
#pragma unroll
        for (int i = 0; i < 4; i++) {
            int g = t + 512 * i;
            int m = g >> 4, s = (g & 15) + h * 16;
            uint32_t off = m * 512 + (uint32_t)((s * 16) ^ ((m & 7) << 4));
            CP16(sINhi + off, inHi + (size_t)(i0 + m) * DD + s * 8);
            CP16(sINlo + off, inLo + (size_t)(i0 + m) * DD + s * 8);
        }
#pragma unroll
        for (int i = 0; i < 2; i++) {
            int gg = t + 512 * i;
            int n = gg >> 4, s = (gg & 15) + h * 16;
            uint32_t off = n * 512 + (uint32_t)((s * 16) ^ ((n & 7) << 4));
            CP16(sW + off, Wh + (size_t)(o0 + n) * DD + s * 8);
        }
    };

    float acc[4][4];
#pragma unroll
    for (int f = 0; f < 4; f++)
#pragma unroll
        for (int q = 0; q < 4; q++) acc[f][q] = 0.f;

    auto comp_half = [&](int h) {
        const int q = lane >> 3, l7 = lane & 7;
#pragma unroll
        for (int ksl = 0; ksl < 8; ksl++) {
            const int ks = h * 8 + ksl;
            uint32_t ah[4], al[4];
            {
                const int m  = wm * 16 + (q & 1) * 8 + l7;
                const int kB = ks * 32 + (q >> 1) * 16;
                const uint32_t off = m * 512 + (uint32_t)(kB ^ ((m & 7) << 4));
                LDSM_X4(ah[0], ah[1], ah[2], ah[3], sINhi + off);
                LDSM_X4(al[0], al[1], al[2], al[3], sINlo + off);
            }
            uint32_t bh[2][4];
#pragma unroll
            for (int nn = 0; nn < 2; nn++) {
                const int n  = wn * 32 + nn * 16 + (q >> 1) * 8 + l7;
                const int kB = ks * 32 + (q & 1) * 16;
                const uint32_t off = n * 512 + (uint32_t)(kB ^ ((n & 7) << 4));
                LDSM_X4(bh[nn][0], bh[nn][1], bh[nn][2], bh[nn][3], sW + off);
            }
#pragma unroll
            for (int nn = 0; nn < 2; nn++) {
                float* d0 = acc[nn * 2];
                float* d1 = acc[nn * 2 + 1];
                MMA_F16(d0, ah[0], ah[1], ah[2], ah[3], bh[nn][0], bh[nn][1]);
                MMA_F16(d0, al[0], al[1], al[2], al[3], bh[nn][0], bh[nn][1]);
                MMA_F16(d1, ah[0], ah[1], ah[2], ah[3], bh[nn][2], bh[nn][3]);
                MMA_F16(d1, al[0], al[1], al[2], al[3], bh[nn][2], bh[nn][3]);
            }
        }
    };

    load_half(0); CP_COMMIT();
    load_half(1); CP_COMMIT();
    asm volatile("cp.async.wait_group 1;" ::: "memory");
    __syncthreads();
    comp_half(0);
    asm volatile("cp.async.wait_group 0;" ::: "memory");
    __syncthreads();
    comp_half(1);

    const int row0 = i0 + wm * 16 + (lane >> 2);
#pragma unroll
    for (int f = 0; f < 4; f++) {
        const int col = o0 + wn * 32 + f * 8 + (lane & 3) * 2;
        const float b0 = bias[col], b1 = bias[col + 1];
        float y00 = fmaxf(acc[f][0] + b0, 0.f);
        float y01 = fmaxf(acc[f][1] + b1, 0.f);
        float y10 = fmaxf(acc[f][2] + b0, 0.f);
        float y11 = fmaxf(acc[f][3] + b1, 0.f);
        if (outF) {
            *reinterpret_cast<float2*>(outF + (size_t)row0 * DD + col) = make_float2(y00, y01);
            *reinterpret_cast<float2*>(outF + (size_t)(row0 + 8) * DD + col) = make_float2(y10, y11);
        } else {
            float y[4] = {y00, y01, y10, y11};
            __half hi[4], lo[4];
#pragma unroll
            for (int j = 0; j < 4; j++) {
                hi[j] = __float2half_rn(y[j]);
                lo[j] = __float2half_rn(y[j] - __half2float(hi[j]));
            }
            *reinterpret_cast<__half2*>(outHi + (size_t)row0 * DD + col) = __halves2half2(hi[0], hi[1]);
            *reinterpret_cast<__half2*>(outHi + (size_t)(row0 + 8) * DD + col) = __halves2half2(hi[2], hi[3]);
            *reinterpret_cast<__half2*>(outLo + (size_t)row0 * DD + col) = __halves2half2(lo[0], lo[1]);
            *reinterpret_cast<__half2*>(outLo + (size_t)(row0 + 8) * DD + col) = __halves2half2(lo[2], lo[3]);
        }
    }
}

// ==================== launch ====================
extern "C" void kernel_launch(void* const* d_in, const int* in_sizes, int n_in,
                              void* d_out, int out_size) {
    const int*   labels = (const int*)d_in[0];
    const int*   nidx   = (const int*)d_in[1];
    const float* A      = (const float*)d_in[2];
    const float* E      = (const float*)d_in[3];
    const float* W      = (const float*)d_in[4];
    const float* bias   = (const float*)d_in[5];

    float* out        = (float*)d_out;
    float* out_labels = nullptr;
    float* out_h      = out;
    if (out_size >= BB * DD + BB) {
        out_labels = out;
        out_h      = out + BB;
    }

    __half *hHi, *hLo, *h2Hi, *h2Lo, *Wh;
    cudaGetSymbolAddress((void**)&hHi,  g_hHi);
    cudaGetSymbolAddress((void**)&hLo,  g_hLo);
    cudaGetSymbolAddress((void**)&h2Hi, g_h2Hi);
    cudaGetSymbolAddress((void**)&h2Lo, g_h2Lo);
    cudaGetSymbolAddress((void**)&Wh,   g_Wh);

    cudaFuncSetAttribute(gemm1_kernel,
                         cudaFuncAttributeMaxDynamicSharedMemorySize, GEMM_SMEM);
    cudaFuncSetAttribute(mlp_kernel,
                         cudaFuncAttributeMaxDynamicSharedMemorySize, MLP_SMEM);

    prep_kernel<<<PREP_GRID, 256>>>(labels, nidx, A, E, W, out_labels);
    gemm1_kernel<<<dim3(KSPLIT, BB / MT), 256, GEMM_SMEM>>>();
    finalize_kernel<<<BB, 64>>>(E);
    mlp_kernel<<<dim3(BB / 128, DD / 64), 512, MLP_SMEM>>>(
        hHi, hLo, Wh, bias, h2Hi, h2Lo, nullptr);
    mlp_kernel<<<dim3(BB / 128, DD / 64), 512, MLP_SMEM>>>(
        h2Hi, h2Lo, Wh + DD * DD, bias + DD, hHi, hLo, nullptr);
    mlp_kernel<<<dim3(BB / 128, DD / 64), 512, MLP_SMEM>>>(
        hHi, hLo, Wh + 2 * DD * DD, bias + 2 * DD, nullptr, nullptr, out_h);
}